// round 3
// baseline (speedup 1.0000x reference)
#include <cuda_runtime.h>
#include <cstdint>

// Problem constants
#define HID    1024
#define NHEAD  16
#define DHEAD  64
#define S_LEN  2048
#define BATCH  2
#define M_TOK  (BATCH * S_LEN)      // 4096 tokens
#define QKV_N  (3 * HID)            // 3072

// Scratch (allocation-free rule: __device__ globals)
__device__ float g_qkv[M_TOK * QKV_N];   // [token][3072] = [token][which*1024 + h*64 + d]
__device__ float g_ctx[M_TOK * HID];     // [token][h*64 + d]

// ---------------------------------------------------------------------------
// GEMM: C[M,N] = A[M,K] * B[N,K]^T + bias[N]
// 128x128 tile, BK=8, 256 threads, 8x8 microtile (split 4+4 rows/cols)
// ---------------------------------------------------------------------------
__global__ __launch_bounds__(256, 2)
void gemm_nt_bias(const float* __restrict__ A, const float* __restrict__ B,
                  const float* __restrict__ bias, float* __restrict__ C,
                  int M, int N, int K)
{
    __shared__ float As[8][128];
    __shared__ float Bs[8][128];

    const int tid = threadIdx.x;
    const int tx = tid & 15;          // 0..15 -> N microtile
    const int ty = tid >> 4;          // 0..15 -> M microtile
    const int bm = blockIdx.y * 128;
    const int bn = blockIdx.x * 128;

    // load indices: each thread one float4 per tile per operand
    const int lrow = tid >> 1;              // 0..127
    const int lcol = (tid & 1) << 2;        // 0 or 4

    const float* Aload = A + (size_t)(bm + lrow) * K + lcol;
    const float* Bload = B + (size_t)(bn + lrow) * K + lcol;

    float acc[8][8];
#pragma unroll
    for (int i = 0; i < 8; i++)
#pragma unroll
        for (int j = 0; j < 8; j++) acc[i][j] = 0.0f;

    for (int k0 = 0; k0 < K; k0 += 8) {
        float4 a = *(const float4*)(Aload + k0);
        float4 b = *(const float4*)(Bload + k0);
        As[lcol + 0][lrow] = a.x;
        As[lcol + 1][lrow] = a.y;
        As[lcol + 2][lrow] = a.z;
        As[lcol + 3][lrow] = a.w;
        Bs[lcol + 0][lrow] = b.x;
        Bs[lcol + 1][lrow] = b.y;
        Bs[lcol + 2][lrow] = b.z;
        Bs[lcol + 3][lrow] = b.w;
        __syncthreads();

#pragma unroll
        for (int kk = 0; kk < 8; kk++) {
            float4 a0 = *(const float4*)&As[kk][ty * 4];
            float4 a1 = *(const float4*)&As[kk][64 + ty * 4];
            float4 b0 = *(const float4*)&Bs[kk][tx * 4];
            float4 b1 = *(const float4*)&Bs[kk][64 + tx * 4];
            float ar[8] = {a0.x, a0.y, a0.z, a0.w, a1.x, a1.y, a1.z, a1.w};
            float br[8] = {b0.x, b0.y, b0.z, b0.w, b1.x, b1.y, b1.z, b1.w};
#pragma unroll
            for (int i = 0; i < 8; i++)
#pragma unroll
                for (int j = 0; j < 8; j++)
                    acc[i][j] += ar[i] * br[j];
        }
        __syncthreads();
    }

    // epilogue with bias
    float4 bi0 = *(const float4*)&bias[bn + tx * 4];
    float4 bi1 = *(const float4*)&bias[bn + 64 + tx * 4];

#pragma unroll
    for (int ih = 0; ih < 2; ih++) {
#pragma unroll
        for (int i = 0; i < 4; i++) {
            int r = bm + ih * 64 + ty * 4 + i;
            int ai = ih * 4 + i;
            float4 o0 = make_float4(acc[ai][0] + bi0.x, acc[ai][1] + bi0.y,
                                    acc[ai][2] + bi0.z, acc[ai][3] + bi0.w);
            float4 o1 = make_float4(acc[ai][4] + bi1.x, acc[ai][5] + bi1.y,
                                    acc[ai][6] + bi1.z, acc[ai][7] + bi1.w);
            *(float4*)&C[(size_t)r * N + bn + tx * 4]      = o0;
            *(float4*)&C[(size_t)r * N + bn + 64 + tx * 4] = o1;
        }
    }
}

// ---------------------------------------------------------------------------
// Flash attention with STATIC shared memory (<48KB, no cudaFuncSetAttribute).
// Per block: one (b,h) x 64 query rows. K/V tiles of 32 rows.
// 256 threads as 16x16; thread (ty,tx) owns S rows 4ty..4ty+3, cols 2tx..2tx+1,
// and O rows 4ty..4ty+3, dims 4tx..4tx+3.
// ---------------------------------------------------------------------------
#define AST 68     // Q/K/V smem row stride (floats)
#define PST 36     // P smem row stride (floats)
#define KT  32     // K/V tile rows

__global__ __launch_bounds__(256)
void attn_kernel(const float* __restrict__ qkv, float* __restrict__ ctx)
{
    __shared__ float Qs[64][AST];   // 17408 B
    __shared__ float Ks[KT][AST];   //  8704 B
    __shared__ float Vs[KT][AST];   //  8704 B
    __shared__ float Ps[64][PST];   //  9216 B   -> total 44032 B

    const int tid = threadIdx.x;
    const int tx = tid & 15;
    const int ty = tid >> 4;
    const int bh = blockIdx.y;
    const int b  = bh >> 4;
    const int h  = bh & 15;
    const int qt = blockIdx.x;          // query tile 0..31
    const float scale = 0.125f;         // 1/sqrt(64)

    // ---- load Q tile (scaled): 64 rows x 64 dims ----
    const float* qb = qkv + (size_t)(b * S_LEN + qt * 64) * QKV_N + h * DHEAD;
#pragma unroll
    for (int l = 0; l < 4; l++) {
        int ff  = tid + l * 256;        // float4 index in 64x16
        int row = ff >> 4;
        int d4  = (ff & 15) << 2;
        float4 v = *(const float4*)(qb + (size_t)row * QKV_N + d4);
        v.x *= scale; v.y *= scale; v.z *= scale; v.w *= scale;
        *(float4*)&Qs[row][d4] = v;
    }

    float o[4][4];
    float mrow[4], lrow[4];
#pragma unroll
    for (int i = 0; i < 4; i++) {
        mrow[i] = -1e30f;
        lrow[i] = 0.0f;
#pragma unroll
        for (int j = 0; j < 4; j++) o[i][j] = 0.0f;
    }

    const float* kb0 = qkv + (size_t)(b * S_LEN) * QKV_N + HID + h * DHEAD;
    const float* vb0 = kb0 + HID;

    for (int kt = 0; kt < S_LEN / KT; kt++) {
        __syncthreads();   // protect Ks/Vs/Ps from previous iteration's readers
        const float* kb = kb0 + (size_t)kt * KT * QKV_N;
        const float* vb = vb0 + (size_t)kt * KT * QKV_N;
        // 32 rows x 16 float4 = 512 float4 per tile; 256 threads x 2
#pragma unroll
        for (int l = 0; l < 2; l++) {
            int ff  = tid + l * 256;
            int row = ff >> 4;
            int d4  = (ff & 15) << 2;
            *(float4*)&Ks[row][d4] = *(const float4*)(kb + (size_t)row * QKV_N + d4);
            *(float4*)&Vs[row][d4] = *(const float4*)(vb + (size_t)row * QKV_N + d4);
        }
        __syncthreads();

        // ---- S = Q * K^T (64x32), each thread 4x2 ----
        float s[4][2];
#pragma unroll
        for (int i = 0; i < 4; i++) { s[i][0] = 0.0f; s[i][1] = 0.0f; }

#pragma unroll
        for (int k0 = 0; k0 < DHEAD; k0 += 4) {
            float4 qv[4], kv[2];
#pragma unroll
            for (int i = 0; i < 4; i++) qv[i] = *(const float4*)&Qs[4 * ty + i][k0];
            kv[0] = *(const float4*)&Ks[2 * tx + 0][k0];
            kv[1] = *(const float4*)&Ks[2 * tx + 1][k0];
#pragma unroll
            for (int i = 0; i < 4; i++)
#pragma unroll
                for (int j = 0; j < 2; j++)
                    s[i][j] += qv[i].x * kv[j].x + qv[i].y * kv[j].y +
                               qv[i].z * kv[j].z + qv[i].w * kv[j].w;
        }

        // ---- online softmax per row (16 lanes per row group) ----
#pragma unroll
        for (int ii = 0; ii < 4; ii++) {
            float tmax = fmaxf(s[ii][0], s[ii][1]);
#pragma unroll
            for (int w = 8; w > 0; w >>= 1)
                tmax = fmaxf(tmax, __shfl_xor_sync(0xffffffffu, tmax, w, 32));
            float mnew = fmaxf(mrow[ii], tmax);
            float fcorr = __expf(mrow[ii] - mnew);
            mrow[ii] = mnew;
            float2 p;
            p.x = __expf(s[ii][0] - mnew);
            p.y = __expf(s[ii][1] - mnew);
            float psum = p.x + p.y;
#pragma unroll
            for (int w = 8; w > 0; w >>= 1)
                psum += __shfl_xor_sync(0xffffffffu, psum, w, 32);
            lrow[ii] = lrow[ii] * fcorr + psum;
            *(float2*)&Ps[4 * ty + ii][2 * tx] = p;
#pragma unroll
            for (int j = 0; j < 4; j++) o[ii][j] *= fcorr;
        }
        __syncthreads();

        // ---- O += P * V  (P: 64x32, V: 32x64) ----
#pragma unroll
        for (int j0 = 0; j0 < KT; j0 += 4) {
            float4 pv[4];
#pragma unroll
            for (int ii = 0; ii < 4; ii++) pv[ii] = *(const float4*)&Ps[4 * ty + ii][j0];
            float4 v0 = *(const float4*)&Vs[j0 + 0][4 * tx];
            float4 v1 = *(const float4*)&Vs[j0 + 1][4 * tx];
            float4 v2 = *(const float4*)&Vs[j0 + 2][4 * tx];
            float4 v3 = *(const float4*)&Vs[j0 + 3][4 * tx];
#pragma unroll
            for (int ii = 0; ii < 4; ii++) {
                o[ii][0] += pv[ii].x * v0.x + pv[ii].y * v1.x + pv[ii].z * v2.x + pv[ii].w * v3.x;
                o[ii][1] += pv[ii].x * v0.y + pv[ii].y * v1.y + pv[ii].z * v2.y + pv[ii].w * v3.y;
                o[ii][2] += pv[ii].x * v0.z + pv[ii].y * v1.z + pv[ii].z * v2.z + pv[ii].w * v3.z;
                o[ii][3] += pv[ii].x * v0.w + pv[ii].y * v1.w + pv[ii].z * v2.w + pv[ii].w * v3.w;
            }
        }
    }

    // ---- finalize: O /= l, write ctx[token][h*64 + d] ----
    float* cb = ctx + (size_t)(b * S_LEN + qt * 64) * HID + h * DHEAD;
#pragma unroll
    for (int ii = 0; ii < 4; ii++) {
        float inv = 1.0f / lrow[ii];
        float4 out = make_float4(o[ii][0] * inv, o[ii][1] * inv,
                                 o[ii][2] * inv, o[ii][3] * inv);
        *(float4*)&cb[(size_t)(4 * ty + ii) * HID + 4 * tx] = out;
    }
}

// ---------------------------------------------------------------------------
extern "C" void kernel_launch(void* const* d_in, const int* in_sizes, int n_in,
                              void* d_out, int out_size)
{
    const float* x     = (const float*)d_in[0];   // [2,2048,1024]
    const float* w_qkv = (const float*)d_in[1];   // [3072,1024]
    const float* b_qkv = (const float*)d_in[2];   // [3072]
    const float* w_out = (const float*)d_in[3];   // [1024,1024]
    const float* b_out = (const float*)d_in[4];   // [1024]
    float* out = (float*)d_out;                   // [2,2048,1024]

    float* qkv_p = nullptr;
    float* ctx_p = nullptr;
    cudaGetSymbolAddress((void**)&qkv_p, g_qkv);
    cudaGetSymbolAddress((void**)&ctx_p, g_ctx);

    // 1) QKV projection: [4096,1024] x [3072,1024]^T + b -> g_qkv
    {
        dim3 grid(QKV_N / 128, M_TOK / 128);
        gemm_nt_bias<<<grid, 256>>>(x, w_qkv, b_qkv, qkv_p, M_TOK, QKV_N, HID);
    }

    // 2) attention -> g_ctx
    {
        dim3 grid(S_LEN / 64, BATCH * NHEAD);
        attn_kernel<<<grid, 256>>>(qkv_p, ctx_p);
    }

    // 3) output projection: [4096,1024] x [1024,1024]^T + b -> out
    {
        dim3 grid(HID / 128, M_TOK / 128);
        gemm_nt_bias<<<grid, 256>>>(ctx_p, w_out, b_out, out, M_TOK, HID, HID);
    }
}

// round 5
// speedup vs baseline: 3.4606x; 3.4606x over previous
#include <cuda_runtime.h>
#include <cstdint>

// Problem constants
#define HID    1024
#define NHEAD  16
#define DHEAD  64
#define S_LEN  2048
#define BATCH  2
#define M_TOK  (BATCH * S_LEN)      // 4096 tokens
#define QKV_N  (3 * HID)            // 3072

// Scratch (allocation-free rule: __device__ globals)
__device__ float g_qkv[M_TOK * QKV_N];   // [token][3072]
__device__ float g_ctx[M_TOK * HID];     // [token][h*64 + d]

// ---------------------------------------------------------------------------
// tf32 helpers
// ---------------------------------------------------------------------------
__device__ __forceinline__ uint32_t f2tf32(float x) {
    uint32_t r;
    asm("cvt.rna.tf32.f32 %0, %1;" : "=r"(r) : "f"(x));
    return r;
}

__device__ __forceinline__ void mma_tf32(float& d0, float& d1, float& d2, float& d3,
                                         uint32_t a0, uint32_t a1, uint32_t a2, uint32_t a3,
                                         uint32_t b0, uint32_t b1) {
    asm volatile(
        "mma.sync.aligned.m16n8k8.row.col.f32.tf32.tf32.f32 "
        "{%0,%1,%2,%3}, {%4,%5,%6,%7}, {%8,%9}, {%0,%1,%2,%3};"
        : "+f"(d0), "+f"(d1), "+f"(d2), "+f"(d3)
        : "r"(a0), "r"(a1), "r"(a2), "r"(a3), "r"(b0), "r"(b1));
}

// ---------------------------------------------------------------------------
// GEMM (tf32 tensor cores): C[M,N] = A[M,K] * B[N,K]^T + bias[N]
// 128x128 tile, BK=32, 256 threads = 8 warps (2m x 4n), warp tile 64x32.
// ---------------------------------------------------------------------------
#define GST 36   // smem k-stride (words): bank = (4*row + k) % 32 -> conflict-free

__global__ __launch_bounds__(256, 2)
void gemm_tf32_nt_bias(const float* __restrict__ A, const float* __restrict__ B,
                       const float* __restrict__ bias, float* __restrict__ C,
                       int M, int N, int K)
{
    __shared__ uint32_t As[128 * GST];
    __shared__ uint32_t Bs[128 * GST];

    const int tid  = threadIdx.x;
    const int w    = tid >> 5;
    const int lane = tid & 31;
    const int g    = lane >> 2;        // group 0..7
    const int tig  = lane & 3;         // thread-in-group 0..3
    const int wm   = w & 1;            // 0..1
    const int wn   = w >> 1;           // 0..3
    const int bm   = blockIdx.y * 128;
    const int bn   = blockIdx.x * 128;

    float acc[4][4][4];                // [mt][nt][c0..c3]
#pragma unroll
    for (int mt = 0; mt < 4; mt++)
#pragma unroll
        for (int nt = 0; nt < 4; nt++)
#pragma unroll
            for (int c = 0; c < 4; c++) acc[mt][nt][c] = 0.0f;

    for (int k0 = 0; k0 < K; k0 += 32) {
        // load 128x32 tiles of A and B, convert to tf32
#pragma unroll
        for (int l = 0; l < 4; l++) {
            int idx = tid + l * 256;           // float4 index in 128x8
            int row = idx >> 3;
            int c4  = (idx & 7) << 2;
            float4 a = *(const float4*)(A + (size_t)(bm + row) * K + k0 + c4);
            float4 b = *(const float4*)(B + (size_t)(bn + row) * K + k0 + c4);
            uint32_t* pa = &As[row * GST + c4];
            uint32_t* pb = &Bs[row * GST + c4];
            pa[0] = f2tf32(a.x); pa[1] = f2tf32(a.y); pa[2] = f2tf32(a.z); pa[3] = f2tf32(a.w);
            pb[0] = f2tf32(b.x); pb[1] = f2tf32(b.y); pb[2] = f2tf32(b.z); pb[3] = f2tf32(b.w);
        }
        __syncthreads();

#pragma unroll
        for (int ks = 0; ks < 4; ks++) {
            const int kk = ks * 8;
            uint32_t af[4][4];
#pragma unroll
            for (int mt = 0; mt < 4; mt++) {
                int r = wm * 64 + mt * 16 + g;
                af[mt][0] = As[(r    ) * GST + kk + tig];
                af[mt][1] = As[(r + 8) * GST + kk + tig];
                af[mt][2] = As[(r    ) * GST + kk + tig + 4];
                af[mt][3] = As[(r + 8) * GST + kk + tig + 4];
            }
#pragma unroll
            for (int nt = 0; nt < 4; nt++) {
                int rb = wn * 32 + nt * 8 + g;
                uint32_t b0 = Bs[rb * GST + kk + tig];
                uint32_t b1 = Bs[rb * GST + kk + tig + 4];
#pragma unroll
                for (int mt = 0; mt < 4; mt++)
                    mma_tf32(acc[mt][nt][0], acc[mt][nt][1], acc[mt][nt][2], acc[mt][nt][3],
                             af[mt][0], af[mt][1], af[mt][2], af[mt][3], b0, b1);
            }
        }
        __syncthreads();
    }

    // epilogue with bias
#pragma unroll
    for (int mt = 0; mt < 4; mt++) {
        int r0 = bm + wm * 64 + mt * 16 + g;
#pragma unroll
        for (int nt = 0; nt < 4; nt++) {
            int col = bn + wn * 32 + nt * 8 + tig * 2;
            float bx = bias[col], by = bias[col + 1];
            float2 v0 = make_float2(acc[mt][nt][0] + bx, acc[mt][nt][1] + by);
            float2 v1 = make_float2(acc[mt][nt][2] + bx, acc[mt][nt][3] + by);
            *(float2*)&C[(size_t)r0 * N + col]       = v0;
            *(float2*)&C[(size_t)(r0 + 8) * N + col] = v1;
        }
    }
}

// ---------------------------------------------------------------------------
// Flash attention (tf32 tensor cores).
// Block = one (b,h), 64 query rows; 128 threads = 4 warps, warp = 16 Q rows.
// KV tiles of 64. Dynamic smem: Qs, Ks, Vt (transposed+swizzled), Ps; stride 68.
// ---------------------------------------------------------------------------
#define AST 68
#define ATT_SMEM (4 * 64 * AST * 4)   // 69632 bytes

__global__ __launch_bounds__(128)
void attn_tf32_kernel(const float* __restrict__ qkv, float* __restrict__ ctx)
{
    extern __shared__ uint32_t sm[];
    uint32_t* Qs = sm;                 // [64][AST]  Q rows (tf32, pre-scaled)
    uint32_t* Ks = sm + 64 * AST;      // [64][AST]  K rows
    uint32_t* Vt = sm + 2 * 64 * AST;  // [64][AST]  V^T: Vt[d][kv_swizzled]
    uint32_t* Ps = sm + 3 * 64 * AST;  // [64][AST]  P rows (tf32)

    const int tid  = threadIdx.x;
    const int w    = tid >> 5;         // warp 0..3 -> Q rows 16w..16w+15
    const int lane = tid & 31;
    const int g    = lane >> 2;
    const int tig  = lane & 3;
    const int wq   = w * 16;

    const int bh = blockIdx.y;
    const int b  = bh >> 4;
    const int h  = bh & 15;
    const int qt = blockIdx.x;
    const float scale = 0.125f;        // 1/sqrt(64)

    // ---- load Q tile (scaled, tf32) ----
    const float* qb = qkv + (size_t)(b * S_LEN + qt * 64) * QKV_N + h * DHEAD;
#pragma unroll
    for (int l = 0; l < 8; l++) {
        int idx = tid + l * 128;       // float4 index in 64x16
        int row = idx >> 4;
        int c4  = (idx & 15) << 2;
        float4 v = *(const float4*)(qb + (size_t)row * QKV_N + c4);
        uint32_t* p = &Qs[row * AST + c4];
        p[0] = f2tf32(v.x * scale); p[1] = f2tf32(v.y * scale);
        p[2] = f2tf32(v.z * scale); p[3] = f2tf32(v.w * scale);
    }

    float oacc[8][4];
    float m0 = -1e30f, m1 = -1e30f, l0 = 0.0f, l1 = 0.0f;
#pragma unroll
    for (int nt = 0; nt < 8; nt++)
#pragma unroll
        for (int c = 0; c < 4; c++) oacc[nt][c] = 0.0f;

    const float* kb0 = qkv + (size_t)(b * S_LEN) * QKV_N + HID + h * DHEAD;
    const float* vb0 = kb0 + HID;

    for (int kt = 0; kt < S_LEN / 64; kt++) {
        __syncthreads();               // protect Ks/Vt from previous readers
        const float* kb = kb0 + (size_t)kt * 64 * QKV_N;
        const float* vb = vb0 + (size_t)kt * 64 * QKV_N;
#pragma unroll
        for (int l = 0; l < 8; l++) {
            int idx = tid + l * 128;
            int row = idx >> 4;        // kv row
            int c4  = (idx & 15) << 2; // d
            float4 kv4 = *(const float4*)(kb + (size_t)row * QKV_N + c4);
            uint32_t* pk = &Ks[row * AST + c4];
            pk[0] = f2tf32(kv4.x); pk[1] = f2tf32(kv4.y);
            pk[2] = f2tf32(kv4.z); pk[3] = f2tf32(kv4.w);
            float4 vv4 = *(const float4*)(vb + (size_t)row * QKV_N + c4);
            float vf[4] = {vv4.x, vv4.y, vv4.z, vv4.w};
#pragma unroll
            for (int i = 0; i < 4; i++) {
                int d = c4 + i;
                int csw = (row + 4 * ((d >> 3) & 7)) & 63;   // swizzled kv column
                Vt[d * AST + csw] = f2tf32(vf[i]);
            }
        }
        __syncthreads();

        // ---- S = Q * K^T : warp computes 16x64, sacc[nt][c] ----
        float sacc[8][4];
#pragma unroll
        for (int nt = 0; nt < 8; nt++)
#pragma unroll
            for (int c = 0; c < 4; c++) sacc[nt][c] = 0.0f;

#pragma unroll
        for (int ks = 0; ks < 8; ks++) {
            const int kk = ks * 8;
            uint32_t a0 = Qs[(wq + g    ) * AST + kk + tig];
            uint32_t a1 = Qs[(wq + g + 8) * AST + kk + tig];
            uint32_t a2 = Qs[(wq + g    ) * AST + kk + tig + 4];
            uint32_t a3 = Qs[(wq + g + 8) * AST + kk + tig + 4];
#pragma unroll
            for (int nt = 0; nt < 8; nt++) {
                uint32_t b0 = Ks[(nt * 8 + g) * AST + kk + tig];
                uint32_t b1 = Ks[(nt * 8 + g) * AST + kk + tig + 4];
                mma_tf32(sacc[nt][0], sacc[nt][1], sacc[nt][2], sacc[nt][3],
                         a0, a1, a2, a3, b0, b1);
            }
        }

        // ---- online softmax: rows r0 = wq+g, r1 = wq+g+8 ----
        float tmax0 = -1e30f, tmax1 = -1e30f;
#pragma unroll
        for (int nt = 0; nt < 8; nt++) {
            tmax0 = fmaxf(tmax0, fmaxf(sacc[nt][0], sacc[nt][1]));
            tmax1 = fmaxf(tmax1, fmaxf(sacc[nt][2], sacc[nt][3]));
        }
        tmax0 = fmaxf(tmax0, __shfl_xor_sync(0xffffffffu, tmax0, 1, 32));
        tmax0 = fmaxf(tmax0, __shfl_xor_sync(0xffffffffu, tmax0, 2, 32));
        tmax1 = fmaxf(tmax1, __shfl_xor_sync(0xffffffffu, tmax1, 1, 32));
        tmax1 = fmaxf(tmax1, __shfl_xor_sync(0xffffffffu, tmax1, 2, 32));

        float m0n = fmaxf(m0, tmax0);
        float m1n = fmaxf(m1, tmax1);
        float fc0 = __expf(m0 - m0n);
        float fc1 = __expf(m1 - m1n);
        m0 = m0n; m1 = m1n;

        float psum0 = 0.0f, psum1 = 0.0f;
        const int r0 = wq + g, r1 = wq + g + 8;
#pragma unroll
        for (int nt = 0; nt < 8; nt++) {
            int c = nt * 8 + 2 * tig;
            float p0 = __expf(sacc[nt][0] - m0n);
            float p1 = __expf(sacc[nt][1] - m0n);
            float p2 = __expf(sacc[nt][2] - m1n);
            float p3 = __expf(sacc[nt][3] - m1n);
            psum0 += p0 + p1;
            psum1 += p2 + p3;
            uint2 u0 = make_uint2(f2tf32(p0), f2tf32(p1));
            uint2 u1 = make_uint2(f2tf32(p2), f2tf32(p3));
            *(uint2*)&Ps[r0 * AST + c] = u0;
            *(uint2*)&Ps[r1 * AST + c] = u1;
        }
        psum0 += __shfl_xor_sync(0xffffffffu, psum0, 1, 32);
        psum0 += __shfl_xor_sync(0xffffffffu, psum0, 2, 32);
        psum1 += __shfl_xor_sync(0xffffffffu, psum1, 1, 32);
        psum1 += __shfl_xor_sync(0xffffffffu, psum1, 2, 32);
        l0 = l0 * fc0 + psum0;
        l1 = l1 * fc1 + psum1;

#pragma unroll
        for (int nt = 0; nt < 8; nt++) {
            oacc[nt][0] *= fc0; oacc[nt][1] *= fc0;
            oacc[nt][2] *= fc1; oacc[nt][3] *= fc1;
        }
        __syncwarp();

        // ---- O += P * V   (P: warp's 16 rows x 64 kv; V^T in Vt) ----
#pragma unroll
        for (int ks = 0; ks < 8; ks++) {
            const int kk = ks * 8;
            uint32_t a0 = Ps[(wq + g    ) * AST + kk + tig];
            uint32_t a1 = Ps[(wq + g + 8) * AST + kk + tig];
            uint32_t a2 = Ps[(wq + g    ) * AST + kk + tig + 4];
            uint32_t a3 = Ps[(wq + g + 8) * AST + kk + tig + 4];
#pragma unroll
            for (int nt = 0; nt < 8; nt++) {
                int c0 = (kk + tig     + 4 * nt) & 63;   // swizzled kv col
                int c1 = (kk + tig + 4 + 4 * nt) & 63;
                uint32_t b0 = Vt[(nt * 8 + g) * AST + c0];
                uint32_t b1 = Vt[(nt * 8 + g) * AST + c1];
                mma_tf32(oacc[nt][0], oacc[nt][1], oacc[nt][2], oacc[nt][3],
                         a0, a1, a2, a3, b0, b1);
            }
        }
    }

    // ---- finalize ----
    float inv0 = 1.0f / l0;
    float inv1 = 1.0f / l1;
    float* cb = ctx + (size_t)(b * S_LEN + qt * 64) * HID + h * DHEAD;
    const int r0 = wq + g, r1 = wq + g + 8;
#pragma unroll
    for (int nt = 0; nt < 8; nt++) {
        int c = nt * 8 + 2 * tig;
        *(float2*)&cb[(size_t)r0 * HID + c] = make_float2(oacc[nt][0] * inv0, oacc[nt][1] * inv0);
        *(float2*)&cb[(size_t)r1 * HID + c] = make_float2(oacc[nt][2] * inv1, oacc[nt][3] * inv1);
    }
}

// ---------------------------------------------------------------------------
extern "C" void kernel_launch(void* const* d_in, const int* in_sizes, int n_in,
                              void* d_out, int out_size)
{
    const float* x     = (const float*)d_in[0];   // [2,2048,1024]
    const float* w_qkv = (const float*)d_in[1];   // [3072,1024]
    const float* b_qkv = (const float*)d_in[2];   // [3072]
    const float* w_out = (const float*)d_in[3];   // [1024,1024]
    const float* b_out = (const float*)d_in[4];   // [1024]
    float* out = (float*)d_out;                   // [2,2048,1024]

    float* qkv_p = nullptr;
    float* ctx_p = nullptr;
    cudaGetSymbolAddress((void**)&qkv_p, g_qkv);
    cudaGetSymbolAddress((void**)&ctx_p, g_ctx);

    cudaFuncSetAttribute(attn_tf32_kernel,
                         cudaFuncAttributeMaxDynamicSharedMemorySize, ATT_SMEM);

    // 1) QKV projection: [4096,1024] x [3072,1024]^T + b -> g_qkv
    {
        dim3 grid(QKV_N / 128, M_TOK / 128);
        gemm_tf32_nt_bias<<<grid, 256>>>(x, w_qkv, b_qkv, qkv_p, M_TOK, QKV_N, HID);
    }

    // 2) attention -> g_ctx
    {
        dim3 grid(S_LEN / 64, BATCH * NHEAD);
        attn_tf32_kernel<<<grid, 128, ATT_SMEM>>>(qkv_p, ctx_p);
    }

    // 3) output projection: [4096,1024] x [1024,1024]^T + b -> out
    {
        dim3 grid(HID / 128, M_TOK / 128);
        gemm_tf32_nt_bias<<<grid, 256>>>(ctx_p, w_out, b_out, out, M_TOK, HID, HID);
    }
}

// round 7
// speedup vs baseline: 3.4823x; 1.0063x over previous
#include <cuda_runtime.h>
#include <cstdint>

// Problem constants
#define HID    1024
#define NHEAD  16
#define DHEAD  64
#define S_LEN  2048
#define BATCH  2
#define M_TOK  (BATCH * S_LEN)      // 4096 tokens
#define QKV_N  (3 * HID)            // 3072

// Scratch (allocation-free rule: __device__ globals)
__device__ float g_qkv[M_TOK * QKV_N];   // [token][3072]
__device__ float g_ctx[M_TOK * HID];     // [token][h*64 + d]

// ---------------------------------------------------------------------------
// helpers
// ---------------------------------------------------------------------------
__device__ __forceinline__ uint32_t f2tf32(float x) {
    uint32_t r;
    asm("cvt.rna.tf32.f32 %0, %1;" : "=r"(r) : "f"(x));
    return r;
}
__device__ __forceinline__ uint32_t tf32_raw(uint32_t bits) {
    uint32_t r;
    asm("cvt.rna.tf32.f32 %0, %1;" : "=r"(r) : "f"(__uint_as_float(bits)));
    return r;
}
__device__ __forceinline__ void mma_tf32(float& d0, float& d1, float& d2, float& d3,
                                         uint32_t a0, uint32_t a1, uint32_t a2, uint32_t a3,
                                         uint32_t b0, uint32_t b1) {
    asm volatile(
        "mma.sync.aligned.m16n8k8.row.col.f32.tf32.tf32.f32 "
        "{%0,%1,%2,%3}, {%4,%5,%6,%7}, {%8,%9}, {%0,%1,%2,%3};"
        : "+f"(d0), "+f"(d1), "+f"(d2), "+f"(d3)
        : "r"(a0), "r"(a1), "r"(a2), "r"(a3), "r"(b0), "r"(b1));
}
__device__ __forceinline__ void cp_async16(void* smem, const void* gmem) {
    uint32_t s = (uint32_t)__cvta_generic_to_shared(smem);
    asm volatile("cp.async.cg.shared.global [%0], [%1], 16;" :: "r"(s), "l"(gmem));
}
__device__ __forceinline__ void cp_commit() {
    asm volatile("cp.async.commit_group;");
}
__device__ __forceinline__ void cp_wait1() {
    asm volatile("cp.async.wait_group 1;");
}
__device__ __forceinline__ void cp_wait0() {
    asm volatile("cp.async.wait_group 0;");
}

// ---------------------------------------------------------------------------
// GEMM (tf32 tensor cores + cp.async double buffer):
// C[M,N] = A[M,K] * B[N,K]^T + bias[N]
// 128x128 tile, BK=32, 256 threads = 8 warps (2m x 4n), warp tile 64x32.
// smem holds RAW fp32; cvt.rna.tf32 applied at fragment load.
// ---------------------------------------------------------------------------
#define GST 36                      // smem k-stride (words)
#define GTS (128 * GST)             // words per tile buffer
#define GEMM_SMEM (4 * GTS * 4)     // 2 stages x (A+B) = 73728 bytes

__global__ __launch_bounds__(256, 2)
void gemm_tf32_nt_bias(const float* __restrict__ A, const float* __restrict__ B,
                       const float* __restrict__ bias, float* __restrict__ C,
                       int M, int N, int K)
{
    extern __shared__ uint32_t gsm[];
    uint32_t* As = gsm;             // [2][GTS]
    uint32_t* Bs = gsm + 2 * GTS;   // [2][GTS]

    const int tid  = threadIdx.x;
    const int w    = tid >> 5;
    const int lane = tid & 31;
    const int g    = lane >> 2;
    const int tig  = lane & 3;
    const int wm   = w & 1;
    const int wn   = w >> 1;
    const int bm   = blockIdx.y * 128;
    const int bn   = blockIdx.x * 128;

    // per-thread load coords (float4 granularity): 1024 float4 per 128x32 tile
    const int lrow = tid >> 1;                   // unused pattern replaced below
    (void)lrow;

    float acc[4][4][4];
#pragma unroll
    for (int mt = 0; mt < 4; mt++)
#pragma unroll
        for (int nt = 0; nt < 4; nt++)
#pragma unroll
            for (int c = 0; c < 4; c++) acc[mt][nt][c] = 0.0f;

    const int nkt = K >> 5;

    // prologue: tile 0 -> stage 0
    {
#pragma unroll
        for (int l = 0; l < 4; l++) {
            int idx = tid + l * 256;
            int row = idx >> 3;
            int c4  = (idx & 7) << 2;
            cp_async16(&As[row * GST + c4], A + (size_t)(bm + row) * K + c4);
            cp_async16(&Bs[row * GST + c4], B + (size_t)(bn + row) * K + c4);
        }
        cp_commit();
    }

    int s = 0;
    for (int kt = 0; kt < nkt; kt++) {
        const bool has_next = (kt + 1) < nkt;
        if (has_next) {
            const int k0 = (kt + 1) << 5;
            uint32_t* An = As + (s ^ 1) * GTS;
            uint32_t* Bn = Bs + (s ^ 1) * GTS;
#pragma unroll
            for (int l = 0; l < 4; l++) {
                int idx = tid + l * 256;
                int row = idx >> 3;
                int c4  = (idx & 7) << 2;
                cp_async16(&An[row * GST + c4], A + (size_t)(bm + row) * K + k0 + c4);
                cp_async16(&Bn[row * GST + c4], B + (size_t)(bn + row) * K + k0 + c4);
            }
            cp_commit();
            cp_wait1();
        } else {
            cp_wait0();
        }
        __syncthreads();

        const uint32_t* Ac = As + s * GTS;
        const uint32_t* Bc = Bs + s * GTS;
#pragma unroll
        for (int ks = 0; ks < 4; ks++) {
            const int kk = ks * 8;
            uint32_t af[4][4];
#pragma unroll
            for (int mt = 0; mt < 4; mt++) {
                int r = wm * 64 + mt * 16 + g;
                af[mt][0] = tf32_raw(Ac[(r    ) * GST + kk + tig]);
                af[mt][1] = tf32_raw(Ac[(r + 8) * GST + kk + tig]);
                af[mt][2] = tf32_raw(Ac[(r    ) * GST + kk + tig + 4]);
                af[mt][3] = tf32_raw(Ac[(r + 8) * GST + kk + tig + 4]);
            }
#pragma unroll
            for (int nt = 0; nt < 4; nt++) {
                int rb = wn * 32 + nt * 8 + g;
                uint32_t b0 = tf32_raw(Bc[rb * GST + kk + tig]);
                uint32_t b1 = tf32_raw(Bc[rb * GST + kk + tig + 4]);
#pragma unroll
                for (int mt = 0; mt < 4; mt++)
                    mma_tf32(acc[mt][nt][0], acc[mt][nt][1], acc[mt][nt][2], acc[mt][nt][3],
                             af[mt][0], af[mt][1], af[mt][2], af[mt][3], b0, b1);
            }
        }
        __syncthreads();
        s ^= 1;
    }

    // epilogue with bias
#pragma unroll
    for (int mt = 0; mt < 4; mt++) {
        int r0 = bm + wm * 64 + mt * 16 + g;
#pragma unroll
        for (int nt = 0; nt < 4; nt++) {
            int col = bn + wn * 32 + nt * 8 + tig * 2;
            float bx = bias[col], by = bias[col + 1];
            float2 v0 = make_float2(acc[mt][nt][0] + bx, acc[mt][nt][1] + by);
            float2 v1 = make_float2(acc[mt][nt][2] + bx, acc[mt][nt][3] + by);
            *(float2*)&C[(size_t)r0 * N + col]       = v0;
            *(float2*)&C[(size_t)(r0 + 8) * N + col] = v1;
        }
    }
}

// ---------------------------------------------------------------------------
// Flash attention (tf32 tensor cores + cp.async double-buffered K/V).
// Block = one (b,h), 64 query rows; 128 threads = 4 warps, warp = 16 Q rows.
// KV tiles of 64. No V transpose: PV B-fragments read raw V rows directly
// (stride 72 -> banks 8*k+g, conflict-free).
// ---------------------------------------------------------------------------
#define AST 72
#define AWD (64 * AST)                  // words per 64-row array
#define ATT_SMEM (6 * AWD * 4)          // Qs,Ps,Ks[2],Vs[2] = 110592 bytes

__global__ __launch_bounds__(128)
void attn_tf32_kernel(const float* __restrict__ qkv, float* __restrict__ ctx)
{
    extern __shared__ uint32_t sm[];
    uint32_t* Qs  = sm;                 // tf32, pre-scaled
    uint32_t* Ps  = sm + AWD;           // tf32
    uint32_t* Ks0 = sm + 2 * AWD;       // raw f32, stage 0
    uint32_t* Ks1 = sm + 3 * AWD;       // raw f32, stage 1
    uint32_t* Vs0 = sm + 4 * AWD;
    uint32_t* Vs1 = sm + 5 * AWD;

    const int tid  = threadIdx.x;
    const int w    = tid >> 5;
    const int lane = tid & 31;
    const int g    = lane >> 2;
    const int tig  = lane & 3;
    const int wq   = w * 16;

    const int bh = blockIdx.y;
    const int b  = bh >> 4;
    const int h  = bh & 15;
    const int qt = blockIdx.x;
    const float scale = 0.125f;         // 1/sqrt(64)

    const float* kb0 = qkv + (size_t)(b * S_LEN) * QKV_N + HID + h * DHEAD;
    const float* vb0 = kb0 + HID;

    // prologue: KV tile 0 -> stage 0
#pragma unroll
    for (int l = 0; l < 8; l++) {
        int idx = tid + l * 128;
        int row = idx >> 4;
        int c4  = (idx & 15) << 2;
        cp_async16(&Ks0[row * AST + c4], kb0 + (size_t)row * QKV_N + c4);
        cp_async16(&Vs0[row * AST + c4], vb0 + (size_t)row * QKV_N + c4);
    }
    cp_commit();

    // load Q tile (scaled, tf32)
    const float* qb = qkv + (size_t)(b * S_LEN + qt * 64) * QKV_N + h * DHEAD;
#pragma unroll
    for (int l = 0; l < 8; l++) {
        int idx = tid + l * 128;
        int row = idx >> 4;
        int c4  = (idx & 15) << 2;
        float4 v = *(const float4*)(qb + (size_t)row * QKV_N + c4);
        uint32_t* p = &Qs[row * AST + c4];
        p[0] = f2tf32(v.x * scale); p[1] = f2tf32(v.y * scale);
        p[2] = f2tf32(v.z * scale); p[3] = f2tf32(v.w * scale);
    }

    float oacc[8][4];
    float m0 = -1e30f, m1 = -1e30f, l0 = 0.0f, l1 = 0.0f;
#pragma unroll
    for (int nt = 0; nt < 8; nt++)
#pragma unroll
        for (int c = 0; c < 4; c++) oacc[nt][c] = 0.0f;

    int s = 0;
    for (int kt = 0; kt < S_LEN / 64; kt++) {
        const bool has_next = (kt + 1) < (S_LEN / 64);
        if (has_next) {
            uint32_t* Kn = (s == 0) ? Ks1 : Ks0;
            uint32_t* Vn = (s == 0) ? Vs1 : Vs0;
            const float* kb = kb0 + (size_t)(kt + 1) * 64 * QKV_N;
            const float* vb = vb0 + (size_t)(kt + 1) * 64 * QKV_N;
#pragma unroll
            for (int l = 0; l < 8; l++) {
                int idx = tid + l * 128;
                int row = idx >> 4;
                int c4  = (idx & 15) << 2;
                cp_async16(&Kn[row * AST + c4], kb + (size_t)row * QKV_N + c4);
                cp_async16(&Vn[row * AST + c4], vb + (size_t)row * QKV_N + c4);
            }
            cp_commit();
            cp_wait1();
        } else {
            cp_wait0();
        }
        __syncthreads();

        const uint32_t* Kc = (s == 0) ? Ks0 : Ks1;
        const uint32_t* Vc = (s == 0) ? Vs0 : Vs1;

        // ---- S = Q * K^T : warp computes 16x64 ----
        float sacc[8][4];
#pragma unroll
        for (int nt = 0; nt < 8; nt++)
#pragma unroll
            for (int c = 0; c < 4; c++) sacc[nt][c] = 0.0f;

#pragma unroll
        for (int ks = 0; ks < 8; ks++) {
            const int kk = ks * 8;
            uint32_t a0 = Qs[(wq + g    ) * AST + kk + tig];
            uint32_t a1 = Qs[(wq + g + 8) * AST + kk + tig];
            uint32_t a2 = Qs[(wq + g    ) * AST + kk + tig + 4];
            uint32_t a3 = Qs[(wq + g + 8) * AST + kk + tig + 4];
#pragma unroll
            for (int nt = 0; nt < 8; nt++) {
                uint32_t b0 = tf32_raw(Kc[(nt * 8 + g) * AST + kk + tig]);
                uint32_t b1 = tf32_raw(Kc[(nt * 8 + g) * AST + kk + tig + 4]);
                mma_tf32(sacc[nt][0], sacc[nt][1], sacc[nt][2], sacc[nt][3],
                         a0, a1, a2, a3, b0, b1);
            }
        }

        // ---- online softmax: rows r0 = wq+g, r1 = wq+g+8 ----
        float tmax0 = -1e30f, tmax1 = -1e30f;
#pragma unroll
        for (int nt = 0; nt < 8; nt++) {
            tmax0 = fmaxf(tmax0, fmaxf(sacc[nt][0], sacc[nt][1]));
            tmax1 = fmaxf(tmax1, fmaxf(sacc[nt][2], sacc[nt][3]));
        }
        tmax0 = fmaxf(tmax0, __shfl_xor_sync(0xffffffffu, tmax0, 1, 32));
        tmax0 = fmaxf(tmax0, __shfl_xor_sync(0xffffffffu, tmax0, 2, 32));
        tmax1 = fmaxf(tmax1, __shfl_xor_sync(0xffffffffu, tmax1, 1, 32));
        tmax1 = fmaxf(tmax1, __shfl_xor_sync(0xffffffffu, tmax1, 2, 32));

        float m0n = fmaxf(m0, tmax0);
        float m1n = fmaxf(m1, tmax1);
        float fc0 = __expf(m0 - m0n);
        float fc1 = __expf(m1 - m1n);
        m0 = m0n; m1 = m1n;

        float psum0 = 0.0f, psum1 = 0.0f;
        const int r0 = wq + g, r1 = wq + g + 8;
#pragma unroll
        for (int nt = 0; nt < 8; nt++) {
            int c = nt * 8 + 2 * tig;
            float p0 = __expf(sacc[nt][0] - m0n);
            float p1 = __expf(sacc[nt][1] - m0n);
            float p2 = __expf(sacc[nt][2] - m1n);
            float p3 = __expf(sacc[nt][3] - m1n);
            psum0 += p0 + p1;
            psum1 += p2 + p3;
            uint2 u0 = make_uint2(f2tf32(p0), f2tf32(p1));
            uint2 u1 = make_uint2(f2tf32(p2), f2tf32(p3));
            *(uint2*)&Ps[r0 * AST + c] = u0;
            *(uint2*)&Ps[r1 * AST + c] = u1;
        }
        psum0 += __shfl_xor_sync(0xffffffffu, psum0, 1, 32);
        psum0 += __shfl_xor_sync(0xffffffffu, psum0, 2, 32);
        psum1 += __shfl_xor_sync(0xffffffffu, psum1, 1, 32);
        psum1 += __shfl_xor_sync(0xffffffffu, psum1, 2, 32);
        l0 = l0 * fc0 + psum0;
        l1 = l1 * fc1 + psum1;

#pragma unroll
        for (int nt = 0; nt < 8; nt++) {
            oacc[nt][0] *= fc0; oacc[nt][1] *= fc0;
            oacc[nt][2] *= fc1; oacc[nt][3] *= fc1;
        }
        __syncwarp();

        // ---- O += P * V  (B-fragments straight from raw V rows) ----
#pragma unroll
        for (int ks = 0; ks < 8; ks++) {
            const int kk = ks * 8;
            uint32_t a0 = Ps[(wq + g    ) * AST + kk + tig];
            uint32_t a1 = Ps[(wq + g + 8) * AST + kk + tig];
            uint32_t a2 = Ps[(wq + g    ) * AST + kk + tig + 4];
            uint32_t a3 = Ps[(wq + g + 8) * AST + kk + tig + 4];
#pragma unroll
            for (int nt = 0; nt < 8; nt++) {
                uint32_t b0 = tf32_raw(Vc[(kk + tig    ) * AST + nt * 8 + g]);
                uint32_t b1 = tf32_raw(Vc[(kk + tig + 4) * AST + nt * 8 + g]);
                mma_tf32(oacc[nt][0], oacc[nt][1], oacc[nt][2], oacc[nt][3],
                         a0, a1, a2, a3, b0, b1);
            }
        }
        __syncthreads();
        s ^= 1;
    }

    // ---- finalize ----
    float inv0 = 1.0f / l0;
    float inv1 = 1.0f / l1;
    float* cb = ctx + (size_t)(b * S_LEN + qt * 64) * HID + h * DHEAD;
    const int r0 = wq + g, r1 = wq + g + 8;
#pragma unroll
    for (int nt = 0; nt < 8; nt++) {
        int c = nt * 8 + 2 * tig;
        *(float2*)&cb[(size_t)r0 * HID + c] = make_float2(oacc[nt][0] * inv0, oacc[nt][1] * inv0);
        *(float2*)&cb[(size_t)r1 * HID + c] = make_float2(oacc[nt][2] * inv1, oacc[nt][3] * inv1);
    }
}

// ---------------------------------------------------------------------------
extern "C" void kernel_launch(void* const* d_in, const int* in_sizes, int n_in,
                              void* d_out, int out_size)
{
    const float* x     = (const float*)d_in[0];   // [2,2048,1024]
    const float* w_qkv = (const float*)d_in[1];   // [3072,1024]
    const float* b_qkv = (const float*)d_in[2];   // [3072]
    const float* w_out = (const float*)d_in[3];   // [1024,1024]
    const float* b_out = (const float*)d_in[4];   // [1024]
    float* out = (float*)d_out;                   // [2,2048,1024]

    float* qkv_p = nullptr;
    float* ctx_p = nullptr;
    cudaGetSymbolAddress((void**)&qkv_p, g_qkv);
    cudaGetSymbolAddress((void**)&ctx_p, g_ctx);

    cudaFuncSetAttribute(gemm_tf32_nt_bias,
                         cudaFuncAttributeMaxDynamicSharedMemorySize, GEMM_SMEM);
    cudaFuncSetAttribute(attn_tf32_kernel,
                         cudaFuncAttributeMaxDynamicSharedMemorySize, ATT_SMEM);

    // 1) QKV projection: [4096,1024] x [3072,1024]^T + b -> g_qkv
    {
        dim3 grid(QKV_N / 128, M_TOK / 128);
        gemm_tf32_nt_bias<<<grid, 256, GEMM_SMEM>>>(x, w_qkv, b_qkv, qkv_p, M_TOK, QKV_N, HID);
    }

    // 2) attention -> g_ctx
    {
        dim3 grid(S_LEN / 64, BATCH * NHEAD);
        attn_tf32_kernel<<<grid, 128, ATT_SMEM>>>(qkv_p, ctx_p);
    }

    // 3) output projection: [4096,1024] x [1024,1024]^T + b -> out
    {
        dim3 grid(HID / 128, M_TOK / 128);
        gemm_tf32_nt_bias<<<grid, 256, GEMM_SMEM>>>(ctx_p, w_out, b_out, out, M_TOK, HID, HID);
    }
}